// round 2
// baseline (speedup 1.0000x reference)
#include <cuda_runtime.h>
#include <math.h>

#define NB 16
#define NL 2048
#define ND 512
#define NE 8
#define NH 8
#define NEH 64
#define NF 2048
#define LN_EPS 1e-5f

// ---------------- static device scratch (no allocations) ----------------
__device__ float g_gates[NB*NE];
__device__ float g_srel [NB*NE];
__device__ float g_qn   [NB*NE*ND];
__device__ float g_qh   [NB*NE*ND];
__device__ float g_qdot [NB*NEH];
__device__ float g_qt   [NB*NEH*ND];
__device__ float g_probs[NB*NEH*NL];     // scores -> probs in place (8MB)
__device__ float g_ctxp [4][NB*NEH*ND];  // L-split partials (deterministic)
__device__ float g_ctx  [NB*NEH*ND];
__device__ float g_attn [NB*NE*ND];
__device__ float g_x    [NB*NE*ND];
__device__ float g_xo   [NB*NE*ND];
__device__ float g_h1t  [NE*NF*NB];      // h1 transposed [e][f][b]
__device__ float g_yp   [4][NB*NE*ND];   // FFN2 f-split partials

// ---------------- packed f32x2 helpers ----------------
__device__ __forceinline__ unsigned long long pk2(float lo, float hi){
    unsigned long long r;
    asm("mov.b64 %0, {%1,%2};" : "=l"(r) : "f"(lo), "f"(hi));
    return r;
}
__device__ __forceinline__ void upk2(unsigned long long v, float& lo, float& hi){
    asm("mov.b64 {%0,%1}, %2;" : "=f"(lo), "=f"(hi) : "l"(v));
}
__device__ __forceinline__ void fma2(unsigned long long& d, unsigned long long a, unsigned long long b){
    asm("fma.rn.f32x2 %0, %1, %2, %0;" : "+l"(d) : "l"(a), "l"(b));
}

// ---------------- block reductions (blockDim.x == 256) ----------------
__device__ __forceinline__ float blkSum(float v){
    __shared__ float sb[8];
    int lane = threadIdx.x & 31, w = threadIdx.x >> 5;
    #pragma unroll
    for(int o=16;o;o>>=1) v += __shfl_xor_sync(0xffffffffu, v, o);
    __syncthreads();
    if(lane==0) sb[w] = v;
    __syncthreads();
    float r = 0.f;
    #pragma unroll
    for(int i=0;i<8;i++) r += sb[i];
    __syncthreads();
    return r;
}
__device__ __forceinline__ float blkMax(float v){
    __shared__ float sb[8];
    int lane = threadIdx.x & 31, w = threadIdx.x >> 5;
    #pragma unroll
    for(int o=16;o;o>>=1) v = fmaxf(v, __shfl_xor_sync(0xffffffffu, v, o));
    __syncthreads();
    if(lane==0) sb[w] = v;
    __syncthreads();
    float r = sb[0];
    #pragma unroll
    for(int i=1;i<8;i++) r = fmaxf(r, sb[i]);
    __syncthreads();
    return r;
}

// ---------------- 1: gates = softmax(query @ w_gate) ----------------
__global__ void k_gates(const float* __restrict__ q, const float* __restrict__ wg){
    int b = blockIdx.x;
    int w = threadIdx.x >> 5, lane = threadIdx.x & 31;
    __shared__ float lg[NE];
    float acc = 0.f;
    for(int d=lane; d<ND; d+=32) acc += q[b*ND+d] * wg[d*NE + w];
    #pragma unroll
    for(int o=16;o;o>>=1) acc += __shfl_xor_sync(0xffffffffu, acc, o);
    if(lane==0) lg[w] = acc;
    __syncthreads();
    if(threadIdx.x==0){
        float m = -1e30f;
        #pragma unroll
        for(int e=0;e<NE;e++) m = fmaxf(m, lg[e]);
        float ex[NE], s = 0.f;
        #pragma unroll
        for(int e=0;e<NE;e++){ ex[e] = expf(lg[e]-m); s += ex[e]; }
        #pragma unroll
        for(int e=0;e<NE;e++) g_gates[b*NE+e] = ex[e]/s;
    }
}

// ---------------- 2: generic per-row LN with per-expert affine ----------------
// row = b*NE + e.  x base: xPerExpert ? x[row*ND] : x[(row>>3)*ND]
__global__ void k_ln(const float* __restrict__ x, const float* __restrict__ gw,
                     const float* __restrict__ bw, float* __restrict__ out,
                     int xPerExpert){
    int row = blockIdx.x, e = row & 7, tid = threadIdx.x;
    const float* xr = x + (size_t)(xPerExpert ? row : (row>>3))*ND;
    __shared__ float xs[ND];
    float s=0.f, ss=0.f;
    for(int d=tid; d<ND; d+=256){ float v = xr[d]; xs[d]=v; s+=v; ss+=v*v; }
    float S  = blkSum(s);
    float SS = blkSum(ss);
    float mu = S * (1.f/ND);
    float rs = rsqrtf(SS*(1.f/ND) - mu*mu + LN_EPS);
    for(int d=tid; d<ND; d+=256){
        float xn = (xs[d]-mu)*rs;
        out[(size_t)row*ND + d] = xn*gw[e*ND+d] + bw[e*ND+d];
    }
}

// ---------------- 3: rowGEMM: out[b,e,k] = in[b,e,:]@W[e,:,k] + bias ----------
// grid (ktile, e); block 256 = 64 k-cols x 4 groups of 4 b
__global__ void k_qhproj(const float* __restrict__ W, const float* __restrict__ bias){
    int e = blockIdx.y, tid = threadIdx.x;
    __shared__ float sm[NB][ND+4];
    for(int i=tid; i<NB*ND; i+=256){
        int b = i >> 9, d = i & 511;
        sm[b][d] = g_qn[(b*NE+e)*ND + d];
    }
    __syncthreads();
    int kl = tid & 63, bg = tid >> 6;
    int k = blockIdx.x*64 + kl, b0 = bg*4;
    float acc[4] = {0,0,0,0};
    const float* wp = W + ((size_t)e<<18) + k;
    #pragma unroll 4
    for(int d=0; d<ND; d++){
        float w = wp[(size_t)d<<9];
        acc[0]+=w*sm[b0  ][d]; acc[1]+=w*sm[b0+1][d];
        acc[2]+=w*sm[b0+2][d]; acc[3]+=w*sm[b0+3][d];
    }
    float bb = bias[e*ND+k];
    #pragma unroll
    for(int j=0;j<4;j++) g_qh[((b0+j)*NE+e)*ND + k] = acc[j] + bb;
}

// ---------------- 4: fold Wk into query: qt, and qdot ----------------
// grid (dtile=16, e); block 256 = 8 h x 32 d
__global__ void k_qt(const float* __restrict__ Wk){
    int e = blockIdx.y, tid = threadIdx.x;
    __shared__ float sm[NB][ND+4];
    for(int i=tid; i<NB*ND; i+=256){
        int b = i >> 9, c = i & 511;
        sm[b][c] = g_qh[(b*NE+e)*ND + c];
    }
    __syncthreads();
    int h = tid >> 5 >> 0; h = tid / 32;     // 0..7
    int dl = tid & 31;
    int d = blockIdx.x*32 + dl;
    const float* wr = Wk + ((size_t)e*ND + d)*ND + h*64;
    float acc[NB];
    #pragma unroll
    for(int b=0;b<NB;b++) acc[b]=0.f;
    #pragma unroll 4
    for(int c=0;c<64;c++){
        float w = wr[c];
        #pragma unroll
        for(int b=0;b<NB;b++) acc[b] += w*sm[b][h*64+c];
    }
    int eh = e*NH + h;
    #pragma unroll
    for(int b=0;b<NB;b++)
        g_qt[((size_t)b*NEH + eh)*ND + d] = acc[b]*0.125f;
}

__global__ void k_qdot(const float* __restrict__ bk){
    int idx = blockIdx.x*256 + threadIdx.x;   // B*E*H = 1024
    int b = idx >> 6, e = (idx >> 3) & 7, h = idx & 7;
    float s = 0.f;
    const float* qp = g_qh + (size_t)(b*NE+e)*ND + h*64;
    const float* bp = bk + e*ND + h*64;
    #pragma unroll 8
    for(int c=0;c<64;c++) s += qp[c]*bp[c];
    g_qdot[b*NEH + e*NH + h] = s*0.125f;
}

// ---------------- shared 64x128 f32x2 micro-kernel step ----------------
__device__ __forceinline__ void mm_step(const float As[16][64], const float Bs[16][128],
                                        unsigned long long acc[4][4], int tm, int tn){
    #pragma unroll
    for(int k=0;k<16;k++){
        float4 a = *(const float4*)&As[k][tm*4];
        unsigned long long a0=pk2(a.x,a.x), a1=pk2(a.y,a.y), a2=pk2(a.z,a.z), a3=pk2(a.w,a.w);
        const ulonglong2* bp = (const ulonglong2*)&Bs[k][tn*8];
        ulonglong2 q0 = bp[0], q1 = bp[1];
        fma2(acc[0][0],a0,q0.x); fma2(acc[0][1],a0,q0.y); fma2(acc[0][2],a0,q1.x); fma2(acc[0][3],a0,q1.y);
        fma2(acc[1][0],a1,q0.x); fma2(acc[1][1],a1,q0.y); fma2(acc[1][2],a1,q1.x); fma2(acc[1][3],a1,q1.y);
        fma2(acc[2][0],a2,q0.x); fma2(acc[2][1],a2,q0.y); fma2(acc[2][2],a2,q1.x); fma2(acc[2][3],a2,q1.y);
        fma2(acc[3][0],a3,q0.x); fma2(acc[3][1],a3,q0.y); fma2(acc[3][2],a3,q1.x); fma2(acc[3][3],a3,q1.y);
    }
}

// ---- 5: scores[b,eh,l] = qt[b,eh,:].retrieved[b,l,:] + qdot  (64x128 tiles) ----
__global__ void k_scores(const float* __restrict__ R){
    int b = blockIdx.y, tid = threadIdx.x;
    __shared__ float As[16][64];
    __shared__ float Bs[16][128];
    const float* A  = g_qt + (size_t)b*NEH*ND;
    const float* Bg = R    + (size_t)b*NL*ND;
    int l0 = blockIdx.x*128;
    int tm = tid >> 4, tn = tid & 15;
    unsigned long long acc[4][4];
    #pragma unroll
    for(int i=0;i<4;i++)
        #pragma unroll
        for(int j=0;j<4;j++) acc[i][j] = 0ull;
    int am = tid >> 2, ak = (tid & 3)*4;
    int bn = tid >> 1, bq = (tid & 1)*8;
    for(int kt=0; kt<ND; kt+=16){
        float4 av = *(const float4*)(A + (size_t)am*ND + kt + ak);
        As[ak  ][am]=av.x; As[ak+1][am]=av.y; As[ak+2][am]=av.z; As[ak+3][am]=av.w;
        const float* brow = Bg + (size_t)(l0+bn)*ND + kt + bq;
        float4 b0v = *(const float4*)(brow);
        float4 b1v = *(const float4*)(brow+4);
        Bs[bq  ][bn]=b0v.x; Bs[bq+1][bn]=b0v.y; Bs[bq+2][bn]=b0v.z; Bs[bq+3][bn]=b0v.w;
        Bs[bq+4][bn]=b1v.x; Bs[bq+5][bn]=b1v.y; Bs[bq+6][bn]=b1v.z; Bs[bq+7][bn]=b1v.w;
        __syncthreads();
        mm_step(As, Bs, acc, tm, tn);
        __syncthreads();
    }
    #pragma unroll
    for(int i=0;i<4;i++){
        int eh = tm*4 + i;
        float qd = g_qdot[b*NEH + eh];
        float* po = g_probs + (size_t)(b*NEH+eh)*NL + l0 + tn*8;
        #pragma unroll
        for(int j=0;j<4;j++){
            float lo, hi; upk2(acc[i][j], lo, hi);
            *(float2*)(po + 2*j) = make_float2(lo+qd, hi+qd);
        }
    }
}

// ---------------- 6: softmax over l (in place) ----------------
__global__ void k_softmax(){
    int row = blockIdx.x, tid = threadIdx.x;
    float* p = g_probs + (size_t)row*NL;
    float v[8];
    float m = -1e30f;
    #pragma unroll
    for(int i=0;i<8;i++){ v[i] = p[tid + i*256]; m = fmaxf(m, v[i]); }
    m = blkMax(m);
    float s = 0.f;
    #pragma unroll
    for(int i=0;i<8;i++){ v[i] = expf(v[i]-m); s += v[i]; }
    s = blkSum(s);
    float inv = 1.f/s;
    #pragma unroll
    for(int i=0;i<8;i++) p[tid + i*256] = v[i]*inv;
}

// ---------------- 7: entropy of head-averaged probs -> srel ----------------
__global__ void k_ent(){
    int e = blockIdx.x, b = blockIdx.y, tid = threadIdx.x;
    const float* pb = g_probs + (size_t)(b*NEH + e*NH)*NL;
    float acc = 0.f;
    for(int l=tid; l<NL; l+=256){
        float s = 0.f;
        #pragma unroll
        for(int h=0;h<NH;h++) s += pb[(size_t)h*NL + l];
        s *= 0.125f;
        s = fmaxf(s, 1e-12f);
        acc -= s*logf(s);
    }
    float Hent = blkSum(acc);
    if(tid==0) g_srel[b*NE+e] = expf(-0.5f*Hent);
}

// ---- 8: ctx[b,eh,d] = sum_l probs*retrieved  (L split by 4, partials) ----
__global__ void k_ctx(const float* __restrict__ R){
    int b = blockIdx.y, z = blockIdx.z, tid = threadIdx.x;
    __shared__ float As[16][64];
    __shared__ float Bs[16][128];
    const float* A  = g_probs + (size_t)b*NEH*NL;
    const float* Bg = R       + (size_t)b*NL*ND;
    int d0 = blockIdx.x*128, lbase = z*512;
    int tm = tid >> 4, tn = tid & 15;
    unsigned long long acc[4][4];
    #pragma unroll
    for(int i=0;i<4;i++)
        #pragma unroll
        for(int j=0;j<4;j++) acc[i][j] = 0ull;
    int am = tid >> 2, ak = (tid & 3)*4;
    int br = tid >> 4, bc = (tid & 15)*8;
    for(int kt=0; kt<512; kt+=16){
        float4 av = *(const float4*)(A + (size_t)am*NL + lbase + kt + ak);
        As[ak  ][am]=av.x; As[ak+1][am]=av.y; As[ak+2][am]=av.z; As[ak+3][am]=av.w;
        const float* brow = Bg + (size_t)(lbase+kt+br)*ND + d0 + bc;
        *(float4*)&Bs[br][bc]   = *(const float4*)(brow);
        *(float4*)&Bs[br][bc+4] = *(const float4*)(brow+4);
        __syncthreads();
        mm_step(As, Bs, acc, tm, tn);
        __syncthreads();
    }
    #pragma unroll
    for(int i=0;i<4;i++){
        int eh = tm*4 + i;
        float* po = g_ctxp[z] + (size_t)(b*NEH+eh)*ND + d0 + tn*8;
        #pragma unroll
        for(int j=0;j<4;j++){
            float lo, hi; upk2(acc[i][j], lo, hi);
            *(float2*)(po + 2*j) = make_float2(lo, hi);
        }
    }
}

__global__ void k_ctxred(){
    int row = blockIdx.x, tid = threadIdx.x;
    #pragma unroll
    for(int it=0; it<2; it++){
        int d = tid + it*256;
        size_t idx = (size_t)row*ND + d;
        g_ctx[idx] = g_ctxp[0][idx] + g_ctxp[1][idx] + g_ctxp[2][idx] + g_ctxp[3][idx];
    }
}

// ---------------- 9: attn[b,e,j] = ctx[b,e*8+h(j),:]@Wv[e,:,j] + bv --------
// grid (h=jtile, e)
__global__ void k_attnv(const float* __restrict__ Wv, const float* __restrict__ bv){
    int e = blockIdx.y, h = blockIdx.x, tid = threadIdx.x;
    __shared__ float sm[NB][ND+4];
    for(int i=tid; i<NB*ND; i+=256){
        int b = i >> 9, d = i & 511;
        sm[b][d] = g_ctx[((size_t)b*NEH + e*NH + h)*ND + d];
    }
    __syncthreads();
    int kl = tid & 63, bg = tid >> 6;
    int j = h*64 + kl, b0 = bg*4;
    float acc[4] = {0,0,0,0};
    const float* wp = Wv + ((size_t)e<<18) + j;
    #pragma unroll 4
    for(int d=0; d<ND; d++){
        float w = wp[(size_t)d<<9];
        acc[0]+=w*sm[b0  ][d]; acc[1]+=w*sm[b0+1][d];
        acc[2]+=w*sm[b0+2][d]; acc[3]+=w*sm[b0+3][d];
    }
    float bb = bv[e*ND+j];
    #pragma unroll
    for(int g=0; g<4; g++) g_attn[((b0+g)*NE+e)*ND + j] = acc[g] + bb;
}

// ---------------- 10: x = query + attn@Wo + bo ----------------
__global__ void k_attno(const float* __restrict__ Wo, const float* __restrict__ bo,
                        const float* __restrict__ q){
    int e = blockIdx.y, tid = threadIdx.x;
    __shared__ float sm[NB][ND+4];
    for(int i=tid; i<NB*ND; i+=256){
        int b = i >> 9, d = i & 511;
        sm[b][d] = g_attn[(b*NE+e)*ND + d];
    }
    __syncthreads();
    int kl = tid & 63, bg = tid >> 6;
    int k = blockIdx.x*64 + kl, b0 = bg*4;
    float acc[4] = {0,0,0,0};
    const float* wp = Wo + ((size_t)e<<18) + k;
    #pragma unroll 4
    for(int d=0; d<ND; d++){
        float w = wp[(size_t)d<<9];
        acc[0]+=w*sm[b0  ][d]; acc[1]+=w*sm[b0+1][d];
        acc[2]+=w*sm[b0+2][d]; acc[3]+=w*sm[b0+3][d];
    }
    float bb = bo[e*ND+k];
    #pragma unroll
    for(int g=0; g<4; g++)
        g_x[((b0+g)*NE+e)*ND + k] = q[(b0+g)*ND + k] + acc[g] + bb;
}

// ---------------- 11: FFN1 h1 = gelu(xo@W1 + b1), store [e][f][b] ----------
// grid (ftile=32, e)
__global__ void k_ffn1(const float* __restrict__ W1, const float* __restrict__ b1){
    int e = blockIdx.y, tid = threadIdx.x;
    __shared__ float sm[NB][ND+4];
    for(int i=tid; i<NB*ND; i+=256){
        int b = i >> 9, d = i & 511;
        sm[b][d] = g_xo[(b*NE+e)*ND + d];
    }
    __syncthreads();
    int kl = tid & 63, bg = tid >> 6;
    int f = blockIdx.x*64 + kl, b0 = bg*4;
    float acc[4] = {0,0,0,0};
    const float* wp = W1 + ((size_t)e*ND)*NF + f;
    #pragma unroll 4
    for(int d=0; d<ND; d++){
        float w = wp[(size_t)d*NF];
        acc[0]+=w*sm[b0  ][d]; acc[1]+=w*sm[b0+1][d];
        acc[2]+=w*sm[b0+2][d]; acc[3]+=w*sm[b0+3][d];
    }
    float bb = b1[e*NF+f];
    #pragma unroll
    for(int g=0; g<4; g++){
        float v = acc[g] + bb;
        float ge = 0.5f*v*(1.f + erff(v*0.70710678118654752f));
        g_h1t[((size_t)e*NF + f)*NB + b0 + g] = ge;
    }
}

// ---------------- 12: FFN2 partials yp[z] = h1@W2 (f chunked) ----------------
// grid (ktile=8, e, z=4)
__global__ void k_ffn2(const float* __restrict__ W2){
    int e = blockIdx.y, z = blockIdx.z, tid = threadIdx.x;
    int kl = tid & 63, bg = tid >> 6;
    int k = blockIdx.x*64 + kl, b0 = bg*4;
    float acc[4] = {0,0,0,0};
    const float* wp = W2 + ((size_t)e*NF)*ND + k;
    const float* hp = g_h1t + (size_t)e*NF*NB + b0;
    int f0 = z*512;
    #pragma unroll 4
    for(int f=f0; f<f0+512; f++){
        float w = wp[(size_t)f<<9];
        float4 hv = *(const float4*)(hp + (size_t)f*NB);
        acc[0]+=w*hv.x; acc[1]+=w*hv.y; acc[2]+=w*hv.z; acc[3]+=w*hv.w;
    }
    #pragma unroll
    for(int g=0; g<4; g++) g_yp[z][((b0+g)*NE+e)*ND + k] = acc[g];
}

// ---------------- 13: y = sum_z yp + b2 + x -> d_out[8192..] ----------------
__global__ void k_yred(const float* __restrict__ b2, float* __restrict__ out){
    int row = blockIdx.x, e = row & 7, tid = threadIdx.x;
    #pragma unroll
    for(int it=0; it<2; it++){
        int k = tid + it*256;
        size_t idx = (size_t)row*ND + k;
        float v = g_yp[0][idx] + g_yp[1][idx] + g_yp[2][idx] + g_yp[3][idx]
                + b2[e*ND+k] + g_x[idx];
        out[NB*ND + idx] = v;   // y region starts after fused (B*D floats)
    }
}

// ---------------- 14: gt, mixture, fused ----------------
__global__ void k_out(float* __restrict__ out){
    int b = blockIdx.x, tid = threadIdx.x;
    __shared__ float gt[NE];
    if(tid==0){
        float s = 0.f, g[NE];
        #pragma unroll
        for(int e=0;e<NE;e++){ g[e] = g_gates[b*NE+e]*g_srel[b*NE+e]; s += g[e]; }
        float inv = 1.f/(s + 1e-9f);
        #pragma unroll
        for(int e=0;e<NE;e++){
            gt[e] = g[e]*inv;
            out[NB*ND + NB*NE*ND + b*NE + e] = gt[e];   // gt region
        }
    }
    __syncthreads();
    const float* y = out + NB*ND;
    #pragma unroll
    for(int it=0; it<2; it++){
        int d = tid + it*256;
        float mix = 0.f;
        #pragma unroll
        for(int e=0;e<NE;e++) mix += gt[e]*y[(size_t)(b*NE+e)*ND + d];
        out[b*ND + d] = mix;    // ALPHA=1 -> fused == mixture
    }
}

// ---------------- launch ----------------
extern "C" void kernel_launch(void* const* d_in, const int* in_sizes, int n_in,
                              void* d_out, int out_size) {
    const float* query  = (const float*)d_in[0];
    const float* retr   = (const float*)d_in[1];
    const float* w_gate = (const float*)d_in[2];
    const float* ln_q_g = (const float*)d_in[3];
    const float* ln_q_b = (const float*)d_in[4];
    const float* Wq     = (const float*)d_in[5];
    const float* bq     = (const float*)d_in[6];
    const float* Wk     = (const float*)d_in[7];
    const float* bk     = (const float*)d_in[8];
    const float* Wv     = (const float*)d_in[9];
    const float* bv     = (const float*)d_in[10];
    const float* Wo     = (const float*)d_in[11];
    const float* bo     = (const float*)d_in[12];
    const float* ln_o_g = (const float*)d_in[13];
    const float* ln_o_b = (const float*)d_in[14];
    const float* W1     = (const float*)d_in[15];
    const float* b1     = (const float*)d_in[16];
    const float* W2     = (const float*)d_in[17];
    const float* b2     = (const float*)d_in[18];
    float* out = (float*)d_out;

    float* p_qn; cudaGetSymbolAddress((void**)&p_qn, g_qn);
    float* p_x;  cudaGetSymbolAddress((void**)&p_x,  g_x);
    float* p_xo; cudaGetSymbolAddress((void**)&p_xo, g_xo);

    k_gates  <<<NB, 256>>>(query, w_gate);
    k_ln     <<<NB*NE, 256>>>(query, ln_q_g, ln_q_b, p_qn, 0);
    k_qhproj <<<dim3(8, NE), 256>>>(Wq, bq);
    k_qt     <<<dim3(16, NE), 256>>>(Wk);
    k_qdot   <<<4, 256>>>(bk);
    k_scores <<<dim3(16, NB), 256>>>(retr);
    k_softmax<<<NB*NEH, 256>>>();
    k_ent    <<<dim3(NE, NB), 256>>>();
    k_ctx    <<<dim3(4, NB, 4), 256>>>(retr);
    k_ctxred <<<NB*NEH, 256>>>();
    k_attnv  <<<dim3(NH, NE), 256>>>(Wv, bv);
    k_attno  <<<dim3(8, NE), 256>>>(Wo, bo, query);
    k_ln     <<<NB*NE, 256>>>(p_x, ln_o_g, ln_o_b, p_xo, 1);
    k_ffn1   <<<dim3(32, NE), 256>>>(W1, b1);
    k_ffn2   <<<dim3(8, NE, 4), 256>>>(W2);
    k_yred   <<<NB*NE, 256>>>(b2, out);
    k_out    <<<NB, 256>>>(out);
}

// round 5
// speedup vs baseline: 1.7576x; 1.7576x over previous
#include <cuda_runtime.h>
#include <math.h>

#define NB 16
#define NL 2048
#define ND 512
#define NE 8
#define NH 8
#define NEH 64
#define NF 2048
#define LN_EPS 1e-5f

// ---------------- static device scratch (no allocations) ----------------
__device__ float g_gates[NB*NE];
__device__ float g_srel [NB*NE];
__device__ float g_qn   [NB*NE*ND];
__device__ float g_qh   [NB*NE*ND];
__device__ float g_qdot [NB*NEH];
__device__ float g_qt   [NB*NEH*ND];
__device__ float g_probs[NB*NEH*NL];     // scores -> probs in place (8MB)
__device__ float g_ctxp [4][NB*NEH*ND];  // L-split partials (deterministic)
__device__ float g_attn [NB*NE*ND];
__device__ float g_x    [NB*NE*ND];
__device__ float g_xo   [NB*NE*ND];
__device__ float g_h1   [NE*NB*NF];      // h1 as [e][b][f]
__device__ float g_part [1048576];       // K-split GEMM partials (4MB)

// ---------------- packed f32x2 helpers ----------------
__device__ __forceinline__ unsigned long long pk2(float lo, float hi){
    unsigned long long r;
    asm("mov.b64 %0, {%1,%2};" : "=l"(r) : "f"(lo), "f"(hi));
    return r;
}
__device__ __forceinline__ void upk2(unsigned long long v, float& lo, float& hi){
    asm("mov.b64 {%0,%1}, %2;" : "=f"(lo), "=f"(hi) : "l"(v));
}
__device__ __forceinline__ void fma2(unsigned long long& d, unsigned long long a, unsigned long long b){
    asm("fma.rn.f32x2 %0, %1, %2, %0;" : "+l"(d) : "l"(a), "l"(b));
}

// ---------------- block reductions (blockDim.x == 256) ----------------
__device__ __forceinline__ float blkSum(float v){
    __shared__ float sb[8];
    int lane = threadIdx.x & 31, w = threadIdx.x >> 5;
    #pragma unroll
    for(int o=16;o;o>>=1) v += __shfl_xor_sync(0xffffffffu, v, o);
    __syncthreads();
    if(lane==0) sb[w] = v;
    __syncthreads();
    float r = 0.f;
    #pragma unroll
    for(int i=0;i<8;i++) r += sb[i];
    __syncthreads();
    return r;
}
__device__ __forceinline__ float blkMax(float v){
    __shared__ float sb[8];
    int lane = threadIdx.x & 31, w = threadIdx.x >> 5;
    #pragma unroll
    for(int o=16;o;o>>=1) v = fmaxf(v, __shfl_xor_sync(0xffffffffu, v, o));
    __syncthreads();
    if(lane==0) sb[w] = v;
    __syncthreads();
    float r = sb[0];
    #pragma unroll
    for(int i=1;i<8;i++) r = fmaxf(r, sb[i]);
    __syncthreads();
    return r;
}

// ---------------- 1: gates = softmax(query @ w_gate) ----------------
__global__ void k_gates(const float* __restrict__ q, const float* __restrict__ wg){
    int b = blockIdx.x;
    int w = threadIdx.x >> 5, lane = threadIdx.x & 31;
    __shared__ float lg[NE];
    float acc = 0.f;
    for(int d=lane; d<ND; d+=32) acc += q[b*ND+d] * wg[d*NE + w];
    #pragma unroll
    for(int o=16;o;o>>=1) acc += __shfl_xor_sync(0xffffffffu, acc, o);
    if(lane==0) lg[w] = acc;
    __syncthreads();
    if(threadIdx.x==0){
        float m = -1e30f;
        #pragma unroll
        for(int e=0;e<NE;e++) m = fmaxf(m, lg[e]);
        float ex[NE], s = 0.f;
        #pragma unroll
        for(int e=0;e<NE;e++){ ex[e] = expf(lg[e]-m); s += ex[e]; }
        #pragma unroll
        for(int e=0;e<NE;e++) g_gates[b*NE+e] = ex[e]/s;
    }
}

// ---------------- 2: per-row LN with per-expert affine ----------------
__global__ void k_ln(const float* __restrict__ x, const float* __restrict__ gw,
                     const float* __restrict__ bw, float* __restrict__ out,
                     int xPerExpert){
    int row = blockIdx.x, e = row & 7, tid = threadIdx.x;
    const float* xr = x + (size_t)(xPerExpert ? row : (row>>3))*ND;
    __shared__ float xs[ND];
    float s=0.f, ss=0.f;
    for(int d=tid; d<ND; d+=256){ float v = xr[d]; xs[d]=v; s+=v; ss+=v*v; }
    float S  = blkSum(s);
    float SS = blkSum(ss);
    float mu = S * (1.f/ND);
    float rs = rsqrtf(SS*(1.f/ND) - mu*mu + LN_EPS);
    for(int d=tid; d<ND; d+=256){
        float xn = (xs[d]-mu)*rs;
        out[(size_t)row*ND + d] = xn*gw[e*ND+d] + bw[e*ND+d];
    }
}

// ---------------- generic K-split skinny GEMM ----------------
// part[z][(b*NE+e)*N + k] = sum_{d in chunk z} in[b,e,d] * W[e,d,k]
// grid (N/256, NE, DS); block 256 = 64 colgroups(x4 via float4) x 4 bgroups(x4 b)
template<int N, int D, int DS>
__global__ void k_gemm(const float* __restrict__ W, const float* __restrict__ in,
                       int strideB, int strideE){
    constexpr int DC = D/DS;
    int e = blockIdx.y, z = blockIdx.z, tid = threadIdx.x;
    __shared__ float xs[NB][DC+1];
    for(int i=tid; i<NB*DC; i+=256){
        int b = i/DC, d = i - b*DC;
        xs[b][d] = in[(size_t)b*strideB + (size_t)e*strideE + z*DC + d];
    }
    __syncthreads();
    int c4 = tid & 63, g = tid >> 6;
    int k = blockIdx.x*256 + c4*4;
    int b0 = g*4;
    float4 a0 = {0,0,0,0}, a1 = {0,0,0,0}, a2 = {0,0,0,0}, a3 = {0,0,0,0};
    const float4* wp = (const float4*)(W + ((size_t)e*D + (size_t)z*DC)*N + k);
    #pragma unroll 4
    for(int d=0; d<DC; d++){
        float4 w = wp[(size_t)d*(N/4)];
        float x0 = xs[b0][d], x1 = xs[b0+1][d], x2 = xs[b0+2][d], x3 = xs[b0+3][d];
        a0.x += w.x*x0; a0.y += w.y*x0; a0.z += w.z*x0; a0.w += w.w*x0;
        a1.x += w.x*x1; a1.y += w.y*x1; a1.z += w.z*x1; a1.w += w.w*x1;
        a2.x += w.x*x2; a2.y += w.y*x2; a2.z += w.z*x2; a2.w += w.w*x2;
        a3.x += w.x*x3; a3.y += w.y*x3; a3.z += w.z*x3; a3.w += w.w*x3;
    }
    float* po = g_part + (size_t)z*(NB*NE*N);
    *(float4*)&po[((size_t)(b0+0)*NE+e)*N + k] = a0;
    *(float4*)&po[((size_t)(b0+1)*NE+e)*N + k] = a1;
    *(float4*)&po[((size_t)(b0+2)*NE+e)*N + k] = a2;
    *(float4*)&po[((size_t)(b0+3)*NE+e)*N + k] = a3;
}

// ---------------- partial reduce + epilogue ----------------
// addMode: 0 none, 1 +query[b*512+k], 2 +addp[idx]
// dstH1: store to [e][b][k] layout (for h1); doGelu: exact gelu
__global__ void k_red(int zc, int N, int Nlog, const float* __restrict__ bias,
                      const float* __restrict__ addp, int addMode,
                      float* __restrict__ dst, int dstH1, int doGelu){
    int idx = blockIdx.x*256 + threadIdx.x;
    int span = NB*NE*N;
    float s = 0.f;
    for(int z=0; z<zc; z++) s += g_part[(size_t)z*span + idx];
    int k = idx & (N-1);
    int r = idx >> Nlog;
    int b = r >> 3, e = r & 7;
    s += bias[e*N + k];
    if(addMode==1)      s += addp[b*ND + k];
    else if(addMode==2) s += addp[idx];
    if(doGelu) s = 0.5f*s*(1.f + erff(s*0.70710678118654752f));
    if(dstH1) dst[((size_t)(e*NB + b))*N + k] = s;
    else      dst[idx] = s;
}

// ---------------- qt: fold Wk into query (static smem, swizzled) ----------------
// qt[b, e*8+h, d] = (1/8) sum_c qh[b,e,h*64+c] * Wk[e,d,h*64+c]
// grid (128 dtiles of 4, NE); block 256 = 8 warps(h); lane = r(4 d-rows) x bg(8, 2 b each)
__global__ void k_qt(const float* __restrict__ Wk){
    __shared__ float qh_s[NB*ND];   // [b*512 + ((c + b) & 511)]  32KB
    __shared__ float wk_s[4*ND];    // [r*512 + ((c + r*8) & 511)] 8KB
    int e = blockIdx.y, tid = threadIdx.x;
    int d0 = blockIdx.x*4;
    for(int i=tid; i<NB*ND; i+=256){
        int b = i >> 9, c = i & 511;
        qh_s[b*ND + ((c + b) & 511)] = g_qh[(b*NE+e)*ND + c];
    }
    for(int j=tid; j<4*128; j+=256){
        int r = j >> 7, c4 = (j & 127)*4;
        float4 v = *(const float4*)(Wk + ((size_t)(e*ND + d0 + r))*ND + c4);
        int base = r*ND, sw = r*8;
        wk_s[base + ((c4+0 + sw)&511)] = v.x;
        wk_s[base + ((c4+1 + sw)&511)] = v.y;
        wk_s[base + ((c4+2 + sw)&511)] = v.z;
        wk_s[base + ((c4+3 + sw)&511)] = v.w;
    }
    __syncthreads();
    int h = tid >> 5, lane = tid & 31;
    int r = lane >> 3, bg = lane & 7;
    int b0 = bg*2;
    float a0 = 0.f, a1 = 0.f;
    #pragma unroll 8
    for(int c0=0; c0<64; c0++){
        int c = h*64 + c0;
        float w = wk_s[r*ND + ((c + r*8)&511)];
        a0 += w * qh_s[(b0  )*ND + ((c + b0  )&511)];
        a1 += w * qh_s[(b0+1)*ND + ((c + b0+1)&511)];
    }
    int d = d0 + r;
    g_qt[((size_t)(b0  )*NEH + e*NH + h)*ND + d] = a0*0.125f;
    g_qt[((size_t)(b0+1)*NEH + e*NH + h)*ND + d] = a1*0.125f;
}

__global__ void k_qdot(const float* __restrict__ bk){
    int idx = blockIdx.x*256 + threadIdx.x;   // B*E*H = 1024
    int b = idx >> 6, e = (idx >> 3) & 7, h = idx & 7;
    float s = 0.f;
    const float* qp = g_qh + (size_t)(b*NE+e)*ND + h*64;
    const float* bp = bk + e*ND + h*64;
    #pragma unroll 8
    for(int c=0;c<64;c++) s += qp[c]*bp[c];
    g_qdot[b*NEH + e*NH + h] = s*0.125f;
}

// ---------------- shared 64x128 f32x2 micro-kernel step ----------------
__device__ __forceinline__ void mm_step(const float As[16][64], const float Bs[16][128],
                                        unsigned long long acc[4][4], int tm, int tn){
    #pragma unroll
    for(int k=0;k<16;k++){
        float4 a = *(const float4*)&As[k][tm*4];
        unsigned long long a0=pk2(a.x,a.x), a1=pk2(a.y,a.y), a2=pk2(a.z,a.z), a3=pk2(a.w,a.w);
        const ulonglong2* bp = (const ulonglong2*)&Bs[k][tn*8];
        ulonglong2 q0 = bp[0], q1 = bp[1];
        fma2(acc[0][0],a0,q0.x); fma2(acc[0][1],a0,q0.y); fma2(acc[0][2],a0,q1.x); fma2(acc[0][3],a0,q1.y);
        fma2(acc[1][0],a1,q0.x); fma2(acc[1][1],a1,q0.y); fma2(acc[1][2],a1,q1.x); fma2(acc[1][3],a1,q1.y);
        fma2(acc[2][0],a2,q0.x); fma2(acc[2][1],a2,q0.y); fma2(acc[2][2],a2,q1.x); fma2(acc[2][3],a2,q1.y);
        fma2(acc[3][0],a3,q0.x); fma2(acc[3][1],a3,q0.y); fma2(acc[3][2],a3,q1.x); fma2(acc[3][3],a3,q1.y);
    }
}

// ---- scores[b,eh,l] = qt[b,eh,:].retrieved[b,l,:] + qdot ----
__global__ void k_scores(const float* __restrict__ R){
    int b = blockIdx.y, tid = threadIdx.x;
    __shared__ float As[16][64];
    __shared__ float Bs[16][128];
    const float* A  = g_qt + (size_t)b*NEH*ND;
    const float* Bg = R    + (size_t)b*NL*ND;
    int l0 = blockIdx.x*128;
    int tm = tid >> 4, tn = tid & 15;
    unsigned long long acc[4][4];
    #pragma unroll
    for(int i=0;i<4;i++)
        #pragma unroll
        for(int j=0;j<4;j++) acc[i][j] = 0ull;
    int am = tid >> 2, ak = (tid & 3)*4;
    int bn = tid >> 1, bq = (tid & 1)*8;
    for(int kt=0; kt<ND; kt+=16){
        float4 av = *(const float4*)(A + (size_t)am*ND + kt + ak);
        As[ak  ][am]=av.x; As[ak+1][am]=av.y; As[ak+2][am]=av.z; As[ak+3][am]=av.w;
        const float* brow = Bg + (size_t)(l0+bn)*ND + kt + bq;
        float4 b0v = *(const float4*)(brow);
        float4 b1v = *(const float4*)(brow+4);
        Bs[bq  ][bn]=b0v.x; Bs[bq+1][bn]=b0v.y; Bs[bq+2][bn]=b0v.z; Bs[bq+3][bn]=b0v.w;
        Bs[bq+4][bn]=b1v.x; Bs[bq+5][bn]=b1v.y; Bs[bq+6][bn]=b1v.z; Bs[bq+7][bn]=b1v.w;
        __syncthreads();
        mm_step(As, Bs, acc, tm, tn);
        __syncthreads();
    }
    #pragma unroll
    for(int i=0;i<4;i++){
        int eh = tm*4 + i;
        float qd = g_qdot[b*NEH + eh];
        float* po = g_probs + (size_t)(b*NEH+eh)*NL + l0 + tn*8;
        #pragma unroll
        for(int j=0;j<4;j++){
            float lo, hi; upk2(acc[i][j], lo, hi);
            *(float2*)(po + 2*j) = make_float2(lo+qd, hi+qd);
        }
    }
}

// ---------------- softmax over l (in place) ----------------
__global__ void k_softmax(){
    int row = blockIdx.x, tid = threadIdx.x;
    float* p = g_probs + (size_t)row*NL;
    float v[8];
    float m = -1e30f;
    #pragma unroll
    for(int i=0;i<8;i++){ v[i] = p[tid + i*256]; m = fmaxf(m, v[i]); }
    m = blkMax(m);
    float s = 0.f;
    #pragma unroll
    for(int i=0;i<8;i++){ v[i] = expf(v[i]-m); s += v[i]; }
    s = blkSum(s);
    float inv = 1.f/s;
    #pragma unroll
    for(int i=0;i<8;i++) p[tid + i*256] = v[i]*inv;
}

// ---------------- entropy of head-averaged probs -> srel ----------------
__global__ void k_ent(){
    int e = blockIdx.x, b = blockIdx.y, tid = threadIdx.x;
    const float* pb = g_probs + (size_t)(b*NEH + e*NH)*NL;
    float acc = 0.f;
    for(int l=tid; l<NL; l+=256){
        float s = 0.f;
        #pragma unroll
        for(int h=0;h<NH;h++) s += pb[(size_t)h*NL + l];
        s *= 0.125f;
        s = fmaxf(s, 1e-12f);
        acc -= s*logf(s);
    }
    float Hent = blkSum(acc);
    if(tid==0) g_srel[b*NE+e] = expf(-0.5f*Hent);
}

// ---- ctx partials: ctxp[z][b,eh,d] = sum_{l in chunk z} probs*retrieved ----
__global__ void k_ctx(const float* __restrict__ R){
    int b = blockIdx.y, z = blockIdx.z, tid = threadIdx.x;
    __shared__ float As[16][64];
    __shared__ float Bs[16][128];
    const float* A  = g_probs + (size_t)b*NEH*NL;
    const float* Bg = R       + (size_t)b*NL*ND;
    int d0 = blockIdx.x*128, lbase = z*512;
    int tm = tid >> 4, tn = tid & 15;
    unsigned long long acc[4][4];
    #pragma unroll
    for(int i=0;i<4;i++)
        #pragma unroll
        for(int j=0;j<4;j++) acc[i][j] = 0ull;
    int am = tid >> 2, ak = (tid & 3)*4;
    int br = tid >> 4, bc = (tid & 15)*8;
    for(int kt=0; kt<512; kt+=16){
        float4 av = *(const float4*)(A + (size_t)am*NL + lbase + kt + ak);
        As[ak  ][am]=av.x; As[ak+1][am]=av.y; As[ak+2][am]=av.z; As[ak+3][am]=av.w;
        const float* brow = Bg + (size_t)(lbase+kt+br)*ND + d0 + bc;
        *(float4*)&Bs[br][bc]   = *(const float4*)(brow);
        *(float4*)&Bs[br][bc+4] = *(const float4*)(brow+4);
        __syncthreads();
        mm_step(As, Bs, acc, tm, tn);
        __syncthreads();
    }
    #pragma unroll
    for(int i=0;i<4;i++){
        int eh = tm*4 + i;
        float* po = g_ctxp[z] + (size_t)(b*NEH+eh)*ND + d0 + tn*8;
        #pragma unroll
        for(int j=0;j<4;j++){
            float lo, hi; upk2(acc[i][j], lo, hi);
            *(float2*)(po + 2*j) = make_float2(lo, hi);
        }
    }
}

// ---- attnv: part[z][(b,e),j] = sum_{d in chunk} ctx[b,e8+h(j),d]*Wv[e,d,j] ----
// grid (h=8, e=8, z=4); block 256 = 16 colgroups(x4) x 16 b
__global__ void k_attnv(const float* __restrict__ Wv){
    int h = blockIdx.x, e = blockIdx.y, z = blockIdx.z, tid = threadIdx.x;
    __shared__ float xs[NB][129];
    for(int i=tid; i<NB*128; i+=256){
        int b = i >> 7, d = i & 127;
        size_t idx = ((size_t)(b*NEH + e*NH + h))*ND + z*128 + d;
        xs[b][d] = g_ctxp[0][idx] + g_ctxp[1][idx] + g_ctxp[2][idx] + g_ctxp[3][idx];
    }
    __syncthreads();
    int c4 = tid & 15, b = tid >> 4;
    int j = h*64 + c4*4;
    float4 a = {0,0,0,0};
    const float4* wp = (const float4*)(Wv + ((size_t)e*ND + z*128)*ND + j);
    #pragma unroll 4
    for(int d=0; d<128; d++){
        float4 w = wp[(size_t)d*(ND/4)];
        float x = xs[b][d];
        a.x += w.x*x; a.y += w.y*x; a.z += w.z*x; a.w += w.w*x;
    }
    float* po = g_part + (size_t)z*(NB*NE*ND);
    *(float4*)&po[((size_t)b*NE+e)*ND + j] = a;
}

// ---------------- final: gt, mixture, fused ----------------
__global__ void k_out(float* __restrict__ out){
    int b = blockIdx.x, tid = threadIdx.x;
    __shared__ float gt[NE];
    if(tid==0){
        float s = 0.f, g[NE];
        #pragma unroll
        for(int e=0;e<NE;e++){ g[e] = g_gates[b*NE+e]*g_srel[b*NE+e]; s += g[e]; }
        float inv = 1.f/(s + 1e-9f);
        #pragma unroll
        for(int e=0;e<NE;e++){
            gt[e] = g[e]*inv;
            out[NB*ND + NB*NE*ND + b*NE + e] = gt[e];
        }
    }
    __syncthreads();
    const float* y = out + NB*ND;
    #pragma unroll
    for(int it=0; it<2; it++){
        int d = tid + it*256;
        float mix = 0.f;
        #pragma unroll
        for(int e=0;e<NE;e++) mix += gt[e]*y[(size_t)(b*NE+e)*ND + d];
        out[b*ND + d] = mix;
    }
}

// ---------------- launch ----------------
extern "C" void kernel_launch(void* const* d_in, const int* in_sizes, int n_in,
                              void* d_out, int out_size) {
    const float* query  = (const float*)d_in[0];
    const float* retr   = (const float*)d_in[1];
    const float* w_gate = (const float*)d_in[2];
    const float* ln_q_g = (const float*)d_in[3];
    const float* ln_q_b = (const float*)d_in[4];
    const float* Wq     = (const float*)d_in[5];
    const float* bq     = (const float*)d_in[6];
    const float* Wk     = (const float*)d_in[7];
    const float* bk     = (const float*)d_in[8];
    const float* Wv     = (const float*)d_in[9];
    const float* bv     = (const float*)d_in[10];
    const float* Wo     = (const float*)d_in[11];
    const float* bo     = (const float*)d_in[12];
    const float* ln_o_g = (const float*)d_in[13];
    const float* ln_o_b = (const float*)d_in[14];
    const float* W1     = (const float*)d_in[15];
    const float* b1     = (const float*)d_in[16];
    const float* W2     = (const float*)d_in[17];
    const float* b2     = (const float*)d_in[18];
    float* out = (float*)d_out;

    float *p_qn, *p_qh, *p_attn, *p_x, *p_xo, *p_h1;
    cudaGetSymbolAddress((void**)&p_qn,   g_qn);
    cudaGetSymbolAddress((void**)&p_qh,   g_qh);
    cudaGetSymbolAddress((void**)&p_attn, g_attn);
    cudaGetSymbolAddress((void**)&p_x,    g_x);
    cudaGetSymbolAddress((void**)&p_xo,   g_xo);
    cudaGetSymbolAddress((void**)&p_h1,   g_h1);

    k_gates  <<<NB, 256>>>(query, w_gate);
    k_ln     <<<NB*NE, 256>>>(query, ln_q_g, ln_q_b, p_qn, 0);

    k_gemm<ND,ND,16> <<<dim3(2, NE, 16), 256>>>(Wq, p_qn, NE*ND, ND);
    k_red    <<<NB*NE*ND/256, 256>>>(16, ND, 9, bq, nullptr, 0, p_qh, 0, 0);

    k_qt     <<<dim3(128, NE), 256>>>(Wk);
    k_qdot   <<<4, 256>>>(bk);

    k_scores <<<dim3(16, NB), 256>>>(retr);
    k_softmax<<<NB*NEH, 256>>>();
    k_ent    <<<dim3(NE, NB), 256>>>();
    k_ctx    <<<dim3(4, NB, 4), 256>>>(retr);

    k_attnv  <<<dim3(NH, NE, 4), 256>>>(Wv);
    k_red    <<<NB*NE*ND/256, 256>>>(4, ND, 9, bv, nullptr, 0, p_attn, 0, 0);

    k_gemm<ND,ND,16> <<<dim3(2, NE, 16), 256>>>(Wo, p_attn, NE*ND, ND);
    k_red    <<<NB*NE*ND/256, 256>>>(16, ND, 9, bo, query, 1, p_x, 0, 0);

    k_ln     <<<NB*NE, 256>>>(p_x, ln_o_g, ln_o_b, p_xo, 1);

    k_gemm<NF,ND,4> <<<dim3(8, NE, 4), 256>>>(W1, p_xo, NE*ND, ND);
    k_red    <<<NB*NE*NF/256, 256>>>(4, NF, 11, b1, nullptr, 0, p_h1, 1, 1);

    k_gemm<ND,NF,16> <<<dim3(2, NE, 16), 256>>>(W2, p_h1, NF, NB*NF);
    k_red    <<<NB*NE*ND/256, 256>>>(16, ND, 9, b2, p_x, 2, out + NB*ND, 0, 0);

    k_out    <<<NB, 256>>>(out);
}

// round 8
// speedup vs baseline: 2.8026x; 1.5945x over previous
#include <cuda_runtime.h>
#include <math.h>
#include <stdint.h>

#define NB 16
#define NL 2048
#define ND 512
#define NE 8
#define NH 8
#define NEH 64
#define NF 2048
#define LN_EPS 1e-5f

// ---------------- static device scratch (no allocations) ----------------
__device__ float g_gates[NB*NE];
__device__ float g_srel [NB*NE];
__device__ float g_qn   [NB*NE*ND];
__device__ float g_qh   [NB*NE*ND];
__device__ float g_qdot [NB*NEH];
__device__ float g_qt   [NB*NEH*ND];
__device__ float g_probs[NB*NEH*NL];     // scores -> probs in place (8MB)
__device__ float g_ctxp [4][NB*NEH*ND];  // L-split partials (deterministic)
__device__ float g_attn [NB*NE*ND];
__device__ float g_x    [NB*NE*ND];
__device__ float g_xo   [NB*NE*ND];
__device__ float g_h1   [NE*NB*NF];      // h1 as [e][b][f]
__device__ float g_part [1048576];       // K-split GEMM partials (4MB)

// ---------------- tf32 helpers ----------------
__device__ __forceinline__ float tf32r(float x){
    uint32_t t;
    asm("cvt.rna.tf32.f32 %0, %1;" : "=r"(t) : "f"(x));
    return __uint_as_float(t);
}
__device__ __forceinline__ void mma_tf32(float* acc, uint32_t a0, uint32_t a1,
                                         uint32_t a2, uint32_t a3,
                                         uint32_t b0, uint32_t b1){
    asm volatile(
        "mma.sync.aligned.m16n8k8.row.col.f32.tf32.tf32.f32 "
        "{%0,%1,%2,%3}, {%4,%5,%6,%7}, {%8,%9}, {%0,%1,%2,%3};"
        : "+f"(acc[0]), "+f"(acc[1]), "+f"(acc[2]), "+f"(acc[3])
        : "r"(a0), "r"(a1), "r"(a2), "r"(a3), "r"(b0), "r"(b1));
}

// ---------------- block reductions (blockDim.x == 256) ----------------
__device__ __forceinline__ float blkSum(float v){
    __shared__ float sb[8];
    int lane = threadIdx.x & 31, w = threadIdx.x >> 5;
    #pragma unroll
    for(int o=16;o;o>>=1) v += __shfl_xor_sync(0xffffffffu, v, o);
    __syncthreads();
    if(lane==0) sb[w] = v;
    __syncthreads();
    float r = 0.f;
    #pragma unroll
    for(int i=0;i<8;i++) r += sb[i];
    __syncthreads();
    return r;
}
__device__ __forceinline__ float blkMax(float v){
    __shared__ float sb[8];
    int lane = threadIdx.x & 31, w = threadIdx.x >> 5;
    #pragma unroll
    for(int o=16;o;o>>=1) v = fmaxf(v, __shfl_xor_sync(0xffffffffu, v, o));
    __syncthreads();
    if(lane==0) sb[w] = v;
    __syncthreads();
    float r = sb[0];
    #pragma unroll
    for(int i=1;i<8;i++) r = fmaxf(r, sb[i]);
    __syncthreads();
    return r;
}

// ---------------- 1: gates = softmax(query @ w_gate) ----------------
__global__ void k_gates(const float* __restrict__ q, const float* __restrict__ wg){
    int b = blockIdx.x;
    int w = threadIdx.x >> 5, lane = threadIdx.x & 31;
    __shared__ float lg[NE];
    float acc = 0.f;
    for(int d=lane; d<ND; d+=32) acc += q[b*ND+d] * wg[d*NE + w];
    #pragma unroll
    for(int o=16;o;o>>=1) acc += __shfl_xor_sync(0xffffffffu, acc, o);
    if(lane==0) lg[w] = acc;
    __syncthreads();
    if(threadIdx.x==0){
        float m = -1e30f;
        #pragma unroll
        for(int e=0;e<NE;e++) m = fmaxf(m, lg[e]);
        float ex[NE], s = 0.f;
        #pragma unroll
        for(int e=0;e<NE;e++){ ex[e] = expf(lg[e]-m); s += ex[e]; }
        #pragma unroll
        for(int e=0;e<NE;e++) g_gates[b*NE+e] = ex[e]/s;
    }
}

// ---------------- 2: per-row LN with per-expert affine ----------------
__global__ void k_ln(const float* __restrict__ x, const float* __restrict__ gw,
                     const float* __restrict__ bw, float* __restrict__ out,
                     int xPerExpert){
    int row = blockIdx.x, e = row & 7, tid = threadIdx.x;
    const float* xr = x + (size_t)(xPerExpert ? row : (row>>3))*ND;
    __shared__ float xs[ND];
    float s=0.f, ss=0.f;
    for(int d=tid; d<ND; d+=256){ float v = xr[d]; xs[d]=v; s+=v; ss+=v*v; }
    float S  = blkSum(s);
    float SS = blkSum(ss);
    float mu = S * (1.f/ND);
    float rs = rsqrtf(SS*(1.f/ND) - mu*mu + LN_EPS);
    for(int d=tid; d<ND; d+=256){
        float xn = (xs[d]-mu)*rs;
        out[(size_t)row*ND + d] = xn*gw[e*ND+d] + bw[e*ND+d];
    }
}

// ---------------- generic K-split skinny GEMM ----------------
template<int N, int D, int DS>
__global__ void k_gemm(const float* __restrict__ W, const float* __restrict__ in,
                       int strideB, int strideE){
    constexpr int DC = D/DS;
    int e = blockIdx.y, z = blockIdx.z, tid = threadIdx.x;
    __shared__ float xs[NB][DC+1];
    for(int i=tid; i<NB*DC; i+=256){
        int b = i/DC, d = i - b*DC;
        xs[b][d] = in[(size_t)b*strideB + (size_t)e*strideE + z*DC + d];
    }
    __syncthreads();
    int c4 = tid & 63, g = tid >> 6;
    int k = blockIdx.x*256 + c4*4;
    int b0 = g*4;
    float4 a0 = {0,0,0,0}, a1 = {0,0,0,0}, a2 = {0,0,0,0}, a3 = {0,0,0,0};
    const float4* wp = (const float4*)(W + ((size_t)e*D + (size_t)z*DC)*N + k);
    #pragma unroll 8
    for(int d=0; d<DC; d++){
        float4 w = wp[(size_t)d*(N/4)];
        float x0 = xs[b0][d], x1 = xs[b0+1][d], x2 = xs[b0+2][d], x3 = xs[b0+3][d];
        a0.x += w.x*x0; a0.y += w.y*x0; a0.z += w.z*x0; a0.w += w.w*x0;
        a1.x += w.x*x1; a1.y += w.y*x1; a1.z += w.z*x1; a1.w += w.w*x1;
        a2.x += w.x*x2; a2.y += w.y*x2; a2.z += w.z*x2; a2.w += w.w*x2;
        a3.x += w.x*x3; a3.y += w.y*x3; a3.z += w.z*x3; a3.w += w.w*x3;
    }
    float* po = g_part + (size_t)z*(NB*NE*N);
    *(float4*)&po[((size_t)(b0+0)*NE+e)*N + k] = a0;
    *(float4*)&po[((size_t)(b0+1)*NE+e)*N + k] = a1;
    *(float4*)&po[((size_t)(b0+2)*NE+e)*N + k] = a2;
    *(float4*)&po[((size_t)(b0+3)*NE+e)*N + k] = a3;
}

// ---------------- partial reduce + epilogue (float4) ----------------
// addMode: 0 none, 1 +query[b*512+k], 2 +addp[idx]
__global__ void k_red(int zc, int N, int Nlog, const float* __restrict__ bias,
                      const float* __restrict__ addp, int addMode,
                      float* __restrict__ dst, int dstH1, int doGelu){
    int i4 = blockIdx.x*256 + threadIdx.x;
    int base = i4*4;
    int span4 = NB*NE*N/4;
    float4 s = {0,0,0,0};
    const float4* gp = (const float4*)g_part;
    #pragma unroll 4
    for(int z=0; z<zc; z++){
        float4 v = gp[(size_t)z*span4 + i4];
        s.x += v.x; s.y += v.y; s.z += v.z; s.w += v.w;
    }
    int k = base & (N-1);
    int r = base >> Nlog;
    int b = r >> 3, e = r & 7;
    float4 bb = *(const float4*)&bias[e*N + k];
    s.x += bb.x; s.y += bb.y; s.z += bb.z; s.w += bb.w;
    if(addMode==1){
        float4 q = *(const float4*)&addp[b*ND + k];
        s.x += q.x; s.y += q.y; s.z += q.z; s.w += q.w;
    } else if(addMode==2){
        float4 q = ((const float4*)addp)[i4];
        s.x += q.x; s.y += q.y; s.z += q.z; s.w += q.w;
    }
    if(doGelu){
        s.x = 0.5f*s.x*(1.f + erff(s.x*0.70710678118654752f));
        s.y = 0.5f*s.y*(1.f + erff(s.y*0.70710678118654752f));
        s.z = 0.5f*s.z*(1.f + erff(s.z*0.70710678118654752f));
        s.w = 0.5f*s.w*(1.f + erff(s.w*0.70710678118654752f));
    }
    if(dstH1) *(float4*)&dst[((size_t)(e*NB + b))*N + k] = s;
    else      ((float4*)dst)[i4] = s;
}

// ---------------- qt: fold Wk into query (+qdot on block x==0) ----------------
__global__ void k_qt(const float* __restrict__ Wk, const float* __restrict__ bk){
    __shared__ float qh_s[NB*ND];   // [b*512 + ((c + b) & 511)]  32KB
    __shared__ float wk_s[4*ND];    // [r*512 + ((c + r*8) & 511)] 8KB
    int e = blockIdx.y, tid = threadIdx.x;
    int d0 = blockIdx.x*4;
    for(int i=tid; i<NB*ND; i+=256){
        int b = i >> 9, c = i & 511;
        qh_s[b*ND + ((c + b) & 511)] = g_qh[(b*NE+e)*ND + c];
    }
    for(int j=tid; j<4*128; j+=256){
        int r = j >> 7, c4 = (j & 127)*4;
        float4 v = *(const float4*)(Wk + ((size_t)(e*ND + d0 + r))*ND + c4);
        int base = r*ND, sw = r*8;
        wk_s[base + ((c4+0 + sw)&511)] = v.x;
        wk_s[base + ((c4+1 + sw)&511)] = v.y;
        wk_s[base + ((c4+2 + sw)&511)] = v.z;
        wk_s[base + ((c4+3 + sw)&511)] = v.w;
    }
    __syncthreads();
    if(blockIdx.x==0 && tid < NB*NH){
        int b = tid >> 3, h = tid & 7;
        float s = 0.f;
        const float* bp = bk + e*ND + h*64;
        #pragma unroll 8
        for(int cc=0; cc<64; cc++){
            int c = h*64 + cc;
            s += qh_s[b*ND + ((c + b)&511)] * bp[cc];
        }
        g_qdot[b*NEH + e*NH + h] = s*0.125f;
    }
    int h = tid >> 5, lane = tid & 31;
    int r = lane >> 3, bg = lane & 7;
    int b0 = bg*2;
    float a0 = 0.f, a1 = 0.f;
    #pragma unroll 8
    for(int c0=0; c0<64; c0++){
        int c = h*64 + c0;
        float w = wk_s[r*ND + ((c + r*8)&511)];
        a0 += w * qh_s[(b0  )*ND + ((c + b0  )&511)];
        a1 += w * qh_s[(b0+1)*ND + ((c + b0+1)&511)];
    }
    int d = d0 + r;
    g_qt[((size_t)(b0  )*NEH + e*NH + h)*ND + d] = a0*0.125f;
    g_qt[((size_t)(b0+1)*NEH + e*NH + h)*ND + d] = a1*0.125f;
}

// ---- scores (tf32 mma): scores[b,eh,l] = qt[b,eh,:].R[b,l,:] + qdot ----
// grid (16 ltiles, NB); block 256 = 8 warps, each warp: 64m x 16n
__global__ void k_scores(const float* __restrict__ R){
    __shared__ float As[64*36];      // [m][k], stride 36
    __shared__ float Bs[128*36];     // [l][k], stride 36
    int b = blockIdx.y, tid = threadIdx.x;
    int l0 = blockIdx.x*128;
    int w = tid >> 5, lane = tid & 31, g = lane >> 2, tr = lane & 3;
    const float* A  = g_qt + (size_t)b*NEH*ND;
    const float* Bg = R    + (size_t)b*NL*ND + (size_t)l0*ND;
    float acc[4][2][4];
    #pragma unroll
    for(int mi=0;mi<4;mi++)
        #pragma unroll
        for(int ni=0;ni<2;ni++)
            #pragma unroll
            for(int c=0;c<4;c++) acc[mi][ni][c] = 0.f;

    int ar = tid >> 2, ac = (tid & 3)*4;       // A stage: row, col-quad
    int brw = tid >> 1, bh = (tid & 1)*16;     // B stage: row, half
    for(int kt=0; kt<ND; kt+=32){
        float4 va0 = *(const float4*)(A + (size_t)ar*ND + kt + ac);
        float4 va1 = *(const float4*)(A + (size_t)ar*ND + kt + 16 + ac);
        float* ap = As + ar*36;
        ap[ac   ]=tf32r(va0.x); ap[ac+1 ]=tf32r(va0.y); ap[ac+2 ]=tf32r(va0.z); ap[ac+3 ]=tf32r(va0.w);
        ap[ac+16]=tf32r(va1.x); ap[ac+17]=tf32r(va1.y); ap[ac+18]=tf32r(va1.z); ap[ac+19]=tf32r(va1.w);
        const float* brp = Bg + (size_t)brw*ND + kt + bh;
        float* bp = Bs + brw*36 + bh;
        #pragma unroll
        for(int q=0;q<4;q++){
            float4 v = *(const float4*)(brp + q*4);
            bp[q*4  ]=tf32r(v.x); bp[q*4+1]=tf32r(v.y); bp[q*4+2]=tf32r(v.z); bp[q*4+3]=tf32r(v.w);
        }
        __syncthreads();
        #pragma unroll
        for(int ks=0; ks<4; ks++){
            int k0 = ks*8;
            uint32_t af[4][4];
            #pragma unroll
            for(int mi=0;mi<4;mi++){
                af[mi][0] = __float_as_uint(As[(mi*16+g  )*36 + k0+tr  ]);
                af[mi][1] = __float_as_uint(As[(mi*16+g+8)*36 + k0+tr  ]);
                af[mi][2] = __float_as_uint(As[(mi*16+g  )*36 + k0+tr+4]);
                af[mi][3] = __float_as_uint(As[(mi*16+g+8)*36 + k0+tr+4]);
            }
            uint32_t bf[2][2];
            #pragma unroll
            for(int ni=0;ni<2;ni++){
                int n0 = w*16 + ni*8;
                bf[ni][0] = __float_as_uint(Bs[(n0+g)*36 + k0+tr  ]);
                bf[ni][1] = __float_as_uint(Bs[(n0+g)*36 + k0+tr+4]);
            }
            #pragma unroll
            for(int mi=0;mi<4;mi++)
                #pragma unroll
                for(int ni=0;ni<2;ni++)
                    mma_tf32(acc[mi][ni], af[mi][0],af[mi][1],af[mi][2],af[mi][3],
                             bf[ni][0], bf[ni][1]);
        }
        __syncthreads();
    }
    #pragma unroll
    for(int mi=0;mi<4;mi++){
        int ehA = mi*16+g, ehB = ehA+8;
        float qdA = g_qdot[b*NEH + ehA];
        float qdB = g_qdot[b*NEH + ehB];
        #pragma unroll
        for(int ni=0;ni<2;ni++){
            int lc = l0 + w*16 + ni*8 + tr*2;
            *(float2*)&g_probs[(size_t)(b*NEH+ehA)*NL + lc] =
                make_float2(acc[mi][ni][0]+qdA, acc[mi][ni][1]+qdA);
            *(float2*)&g_probs[(size_t)(b*NEH+ehB)*NL + lc] =
                make_float2(acc[mi][ni][2]+qdB, acc[mi][ni][3]+qdB);
        }
    }
}

// ---------------- softmax over l + entropy (fused) ----------------
// grid NB*NE; block 256; each block does the 8 head-rows of one (b,e)
__global__ void k_softent(){
    __shared__ float sump[NL];   // 8KB
    int be = blockIdx.x, tid = threadIdx.x;
    for(int i=tid; i<NL; i+=256) sump[i] = 0.f;
    __syncthreads();
    for(int h=0; h<NH; h++){
        float* p = g_probs + (size_t)(be*NH + h)*NL;
        float v[8];
        float m = -1e30f;
        #pragma unroll
        for(int i=0;i<8;i++){ v[i] = p[tid + i*256]; m = fmaxf(m, v[i]); }
        m = blkMax(m);
        float s = 0.f;
        #pragma unroll
        for(int i=0;i<8;i++){ v[i] = expf(v[i]-m); s += v[i]; }
        s = blkSum(s);
        float inv = 1.f/s;
        #pragma unroll
        for(int i=0;i<8;i++){
            float pv = v[i]*inv;
            p[tid + i*256] = pv;
            sump[tid + i*256] += pv;
        }
        __syncthreads();
    }
    float acc = 0.f;
    for(int i=tid; i<NL; i+=256){
        float sv = fmaxf(sump[i]*0.125f, 1e-12f);
        acc -= sv*logf(sv);
    }
    float Hent = blkSum(acc);
    if(tid==0) g_srel[be] = expf(-0.5f*Hent);
}

// ---- ctx (tf32 mma): ctxp[z][b,eh,d] = sum_{l in chunk z} probs*R ----
// grid (4 dtiles, NB, 4 z); block 256 = 8 warps, each warp: 64m x 16n
__global__ void k_ctx(const float* __restrict__ R){
    __shared__ float As[64*36];      // [m(eh)][k(l)], stride 36
    __shared__ float Bs[32*136];     // [k(l)][n(d)], stride 136
    int b = blockIdx.y, z = blockIdx.z, tid = threadIdx.x;
    int d0 = blockIdx.x*128, lbase = z*512;
    int w = tid >> 5, lane = tid & 31, g = lane >> 2, tr = lane & 3;
    const float* A  = g_probs + (size_t)b*NEH*NL + lbase;
    const float* Bg = R       + (size_t)b*NL*ND + (size_t)lbase*ND + d0;
    float acc[4][2][4];
    #pragma unroll
    for(int mi=0;mi<4;mi++)
        #pragma unroll
        for(int ni=0;ni<2;ni++)
            #pragma unroll
            for(int c=0;c<4;c++) acc[mi][ni][c] = 0.f;

    int ar = tid >> 2, ac = (tid & 3)*4;     // A stage
    int brw = tid >> 3, bseg = (tid & 7)*16; // B stage: row k, 16-col seg
    for(int kt=0; kt<512; kt+=32){
        float4 va0 = *(const float4*)(A + (size_t)ar*NL + kt + ac);
        float4 va1 = *(const float4*)(A + (size_t)ar*NL + kt + 16 + ac);
        float* ap = As + ar*36;
        ap[ac   ]=tf32r(va0.x); ap[ac+1 ]=tf32r(va0.y); ap[ac+2 ]=tf32r(va0.z); ap[ac+3 ]=tf32r(va0.w);
        ap[ac+16]=tf32r(va1.x); ap[ac+17]=tf32r(va1.y); ap[ac+18]=tf32r(va1.z); ap[ac+19]=tf32r(va1.w);
        const float* brp = Bg + (size_t)(kt+brw)*ND + bseg;
        float* bp = Bs + brw*136 + bseg;
        #pragma unroll
        for(int q=0;q<4;q++){
            float4 v = *(const float4*)(brp + q*4);
            bp[q*4  ]=tf32r(v.x); bp[q*4+1]=tf32r(v.y); bp[q*4+2]=tf32r(v.z); bp[q*4+3]=tf32r(v.w);
        }
        __syncthreads();
        #pragma unroll
        for(int ks=0; ks<4; ks++){
            int k0 = ks*8;
            uint32_t af[4][4];
            #pragma unroll
            for(int mi=0;mi<4;mi++){
                af[mi][0] = __float_as_uint(As[(mi*16+g  )*36 + k0+tr  ]);
                af[mi][1] = __float_as_uint(As[(mi*16+g+8)*36 + k0+tr  ]);
                af[mi][2] = __float_as_uint(As[(mi*16+g  )*36 + k0+tr+4]);
                af[mi][3] = __float_as_uint(As[(mi*16+g+8)*36 + k0+tr+4]);
            }
            uint32_t bf[2][2];
            #pragma unroll
            for(int ni=0;ni<2;ni++){
                int n0 = w*16 + ni*8;
                bf[ni][0] = __float_as_uint(Bs[(k0+tr  )*136 + n0+g]);
                bf[ni][1] = __float_as_uint(Bs[(k0+tr+4)*136 + n0+g]);
            }
            #pragma unroll
            for(int mi=0;mi<4;mi++)
                #pragma unroll
                for(int ni=0;ni<2;ni++)
                    mma_tf32(acc[mi][ni], af[mi][0],af[mi][1],af[mi][2],af[mi][3],
                             bf[ni][0], bf[ni][1]);
        }
        __syncthreads();
    }
    float* po = g_ctxp[z];
    #pragma unroll
    for(int mi=0;mi<4;mi++){
        int ehA = mi*16+g, ehB = ehA+8;
        #pragma unroll
        for(int ni=0;ni<2;ni++){
            int dc = d0 + w*16 + ni*8 + tr*2;
            *(float2*)&po[(size_t)(b*NEH+ehA)*ND + dc] =
                make_float2(acc[mi][ni][0], acc[mi][ni][1]);
            *(float2*)&po[(size_t)(b*NEH+ehB)*ND + dc] =
                make_float2(acc[mi][ni][2], acc[mi][ni][3]);
        }
    }
}

// ---- attnv: part[z][(b,e),j] = sum_{d in chunk} ctx[b,e8+h(j),d]*Wv[e,d,j] ----
__global__ void k_attnv(const float* __restrict__ Wv){
    int h = blockIdx.x, e = blockIdx.y, z = blockIdx.z, tid = threadIdx.x;
    __shared__ float xs[NB][129];
    for(int i=tid; i<NB*128; i+=256){
        int b = i >> 7, d = i & 127;
        size_t idx = ((size_t)(b*NEH + e*NH + h))*ND + z*128 + d;
        xs[b][d] = g_ctxp[0][idx] + g_ctxp[1][idx] + g_ctxp[2][idx] + g_ctxp[3][idx];
    }
    __syncthreads();
    int c4 = tid & 15, b = tid >> 4;
    int j = h*64 + c4*4;
    float4 a = {0,0,0,0};
    const float4* wp = (const float4*)(Wv + ((size_t)e*ND + z*128)*ND + j);
    #pragma unroll 8
    for(int d=0; d<128; d++){
        float4 w = wp[(size_t)d*(ND/4)];
        float x = xs[b][d];
        a.x += w.x*x; a.y += w.y*x; a.z += w.z*x; a.w += w.w*x;
    }
    float* po = g_part + (size_t)z*(NB*NE*ND);
    *(float4*)&po[((size_t)b*NE+e)*ND + j] = a;
}

// ---------------- final: gt, mixture, fused ----------------
__global__ void k_out(float* __restrict__ out){
    int b = blockIdx.x, tid = threadIdx.x;
    __shared__ float gt[NE];
    if(tid==0){
        float s = 0.f, g[NE];
        #pragma unroll
        for(int e=0;e<NE;e++){ g[e] = g_gates[b*NE+e]*g_srel[b*NE+e]; s += g[e]; }
        float inv = 1.f/(s + 1e-9f);
        #pragma unroll
        for(int e=0;e<NE;e++){
            gt[e] = g[e]*inv;
            out[NB*ND + NB*NE*ND + b*NE + e] = gt[e];
        }
    }
    __syncthreads();
    const float* y = out + NB*ND;
    #pragma unroll
    for(int it=0; it<2; it++){
        int d = tid + it*256;
        float mix = 0.f;
        #pragma unroll
        for(int e=0;e<NE;e++) mix += gt[e]*y[(size_t)(b*NE+e)*ND + d];
        out[b*ND + d] = mix;
    }
}

// ---------------- launch ----------------
extern "C" void kernel_launch(void* const* d_in, const int* in_sizes, int n_in,
                              void* d_out, int out_size) {
    const float* query  = (const float*)d_in[0];
    const float* retr   = (const float*)d_in[1];
    const float* w_gate = (const float*)d_in[2];
    const float* ln_q_g = (const float*)d_in[3];
    const float* ln_q_b = (const float*)d_in[4];
    const float* Wq     = (const float*)d_in[5];
    const float* bq     = (const float*)d_in[6];
    const float* Wk     = (const float*)d_in[7];
    const float* bk     = (const float*)d_in[8];
    const float* Wv     = (const float*)d_in[9];
    const float* bv     = (const float*)d_in[10];
    const float* Wo     = (const float*)d_in[11];
    const float* bo     = (const float*)d_in[12];
    const float* ln_o_g = (const float*)d_in[13];
    const float* ln_o_b = (const float*)d_in[14];
    const float* W1     = (const float*)d_in[15];
    const float* b1     = (const float*)d_in[16];
    const float* W2     = (const float*)d_in[17];
    const float* b2     = (const float*)d_in[18];
    float* out = (float*)d_out;

    float *p_qn, *p_qh, *p_attn, *p_x, *p_xo, *p_h1;
    cudaGetSymbolAddress((void**)&p_qn,   g_qn);
    cudaGetSymbolAddress((void**)&p_qh,   g_qh);
    cudaGetSymbolAddress((void**)&p_attn, g_attn);
    cudaGetSymbolAddress((void**)&p_x,    g_x);
    cudaGetSymbolAddress((void**)&p_xo,   g_xo);
    cudaGetSymbolAddress((void**)&p_h1,   g_h1);

    k_gates  <<<NB, 256>>>(query, w_gate);
    k_ln     <<<NB*NE, 256>>>(query, ln_q_g, ln_q_b, p_qn, 0);

    k_gemm<ND,ND,16> <<<dim3(2, NE, 16), 256>>>(Wq, p_qn, NE*ND, ND);
    k_red    <<<NB*NE*ND/1024, 256>>>(16, ND, 9, bq, nullptr, 0, p_qh, 0, 0);

    k_qt     <<<dim3(128, NE), 256>>>(Wk, bk);

    k_scores <<<dim3(16, NB), 256>>>(retr);
    k_softent<<<NB*NE, 256>>>();
    k_ctx    <<<dim3(4, NB, 4), 256>>>(retr);

    k_attnv  <<<dim3(NH, NE, 4), 256>>>(Wv);
    k_red    <<<NB*NE*ND/1024, 256>>>(4, ND, 9, bv, nullptr, 0, p_attn, 0, 0);

    k_gemm<ND,ND,16> <<<dim3(2, NE, 16), 256>>>(Wo, p_attn, NE*ND, ND);
    k_red    <<<NB*NE*ND/1024, 256>>>(16, ND, 9, bo, query, 1, p_x, 0, 0);

    k_ln     <<<NB*NE, 256>>>(p_x, ln_o_g, ln_o_b, p_xo, 1);

    k_gemm<NF,ND,4> <<<dim3(8, NE, 4), 256>>>(W1, p_xo, NE*ND, ND);
    k_red    <<<NB*NE*NF/1024, 256>>>(4, NF, 11, b1, nullptr, 0, p_h1, 1, 1);

    k_gemm<ND,NF,16> <<<dim3(2, NE, 16), 256>>>(W2, p_h1, NF, NB*NF);
    k_red    <<<NB*NE*ND/1024, 256>>>(16, ND, 9, b2, p_x, 2, out + NB*ND, 0, 0);

    k_out    <<<NB, 256>>>(out);
}